// round 13
// baseline (speedup 1.0000x reference)
#include <cuda_runtime.h>
#include <cuda_bf16.h>

// -----------------------------------------------------------------------------
// FrustumSegmentationNet — collapsed exact-math, ONE kernel, fully parallel
// per-block prep (R11 structure), 2 sequential quads per thread.
//
// R0 proof: FPS argmin always selects index 0 -> all groups identical ->
// axis-0 batchnorms collapse feats to the constant fc = bd3 + relu(be5)@Wd3^T.
// Output = per-pixel 6->80 linear with Kinv folded into per-channel (A,B,C)
// + folded bias; zero outside the box.
//
// R13: revert R12 prep experiments (they regressed); keep R11 prep verbatim.
// Halve block count (320 x 256): each thread runs the proven pixel body for
// two quads SEQUENTIALLY (#pragma unroll 1 -> R11 register footprint), so the
// per-block prep tax is paid half as often (2.2 block-waves/SM vs 4.3).
// -----------------------------------------------------------------------------

#define HWPIX  65536
#define NCH    80

typedef unsigned long long u64;

__device__ __forceinline__ u64 pk2(float x) {
    u64 r; asm("mov.b64 %0, {%1, %1};" : "=l"(r) : "f"(x)); return r;
}
__device__ __forceinline__ u64 pair2(float lo, float hi) {
    u64 r; asm("mov.b64 %0, {%1, %2};" : "=l"(r) : "f"(lo), "f"(hi)); return r;
}
__device__ __forceinline__ u64 fma2(u64 a, u64 b, u64 c) {
    u64 d; asm("fma.rn.f32x2 %0, %1, %2, %3;" : "=l"(d) : "l"(a), "l"(b), "l"(c));
    return d;
}
__device__ __forceinline__ float warp_sum(float s) {
    #pragma unroll
    for (int off = 16; off > 0; off >>= 1)
        s += __shfl_down_sync(0xFFFFFFFFu, s, off);
    return s;
}

__global__ __launch_bounds__(256, 4)
void frustum_all_kernel(const float* __restrict__ rgb,    // (H,W,3)
                        const float* __restrict__ depth,  // (H,W)
                        const float* __restrict__ intr,   // (3,3)
                        const int*   __restrict__ box,    // (5)
                        const float* __restrict__ be5,    // (256)
                        const float* __restrict__ Wd3,    // (128,256)
                        const float* __restrict__ bd3,    // (128)
                        const float* __restrict__ Ws,     // (80,134)
                        const float* __restrict__ bs,     // (80)
                        float* __restrict__ out)          // (80,H,W)
{
    // blob first (LDS.128-accessed -> 16B aligned):
    // per channel: [A,A, B,B, C,C, w3,w3, w4,w4, w5,w5, bias,bias, 0,0]
    __shared__ __align__(16) float sP[8 * 16];
    __shared__ __align__(16) float sfc[128];
    __shared__ __align__(16) float sbe[256];
    __shared__ __align__(16) float sbias[8];
    __shared__ __align__(16) float sK[12];
    __shared__ __align__(16) float soff[4];
    __shared__ __align__(16) int   sbox[4];

    const int t     = threadIdx.x;
    const int warp  = t >> 5;
    const int lane  = t & 31;
    const int blk   = blockIdx.x;
    const int g     = blk >> 5;            // channel group (32 blocks per group)
    const int cbase = g * 8;

    // ---- per-block prep (R11-verbatim) ----
    float bev = fmaxf(be5[t], 0.0f);
    sbe[t] = bev;
    if (t == 0) {
        float a = intr[0], b = intr[1], c = intr[2];
        float d = intr[3], e = intr[4], f = intr[5];
        float gg = intr[6], h = intr[7], i9 = intr[8];
        float det = a * (e * i9 - f * h) - b * (d * i9 - f * gg) + c * (d * h - e * gg);
        float inv = 1.0f / det;
        sK[0] = (e * i9 - f * h) * inv;  sK[1] = (c * h - b * i9) * inv;  sK[2] = (b * f - c * e) * inv;
        sK[3] = (f * gg - d * i9) * inv; sK[4] = (a * i9 - c * gg) * inv; sK[5] = (c * d - a * f) * inv;
        sK[6] = (d * h - e * gg) * inv;  sK[7] = (b * gg - a * h) * inv;  sK[8] = (a * e - b * d) * inv;
        int b0 = box[0], b1 = box[1], b2 = box[2], b3 = box[3];
        sbox[0] = b0; sbox[1] = b1; sbox[2] = b2; sbox[3] = b3;
        soff[0] = 0.5f - (float)b1;    // u offset (col)
        soff[1] = 0.5f - (float)b0;    // v offset (row)
    }
    const int any_pos = __syncthreads_or(bev > 0.0f);

    if (!any_pos) {
        // fast path (bit-exact): relu(be5) == 0 -> fc = bd3
        if (t < 128) sfc[t] = bd3[t];
        __syncthreads();
    } else {
        // general fallback: fc[j] = bd3[j] + relu(be5) . Wd3[j,:]
        #pragma unroll
        for (int bb = 0; bb < 4; bb++) {
            int j0 = warp * 16 + bb * 4;
            const float4* r0 = reinterpret_cast<const float4*>(Wd3 + (j0 + 0) * 256);
            const float4* r1 = reinterpret_cast<const float4*>(Wd3 + (j0 + 1) * 256);
            const float4* r2 = reinterpret_cast<const float4*>(Wd3 + (j0 + 2) * 256);
            const float4* r3 = reinterpret_cast<const float4*>(Wd3 + (j0 + 3) * 256);
            float4 a0 = r0[lane], b0v = r0[lane + 32];
            float4 a1 = r1[lane], b1v = r1[lane + 32];
            float4 a2 = r2[lane], b2v = r2[lane + 32];
            float4 a3 = r3[lane], b3v = r3[lane + 32];
            int k0 = 4 * lane, k1 = 128 + 4 * lane;
            float e0 = sbe[k0], e1 = sbe[k0+1], e2 = sbe[k0+2], e3 = sbe[k0+3];
            float f0 = sbe[k1], f1 = sbe[k1+1], f2 = sbe[k1+2], f3 = sbe[k1+3];
            float s0 = a0.x*e0 + a0.y*e1 + a0.z*e2 + a0.w*e3 + b0v.x*f0 + b0v.y*f1 + b0v.z*f2 + b0v.w*f3;
            float s1 = a1.x*e0 + a1.y*e1 + a1.z*e2 + a1.w*e3 + b1v.x*f0 + b1v.y*f1 + b1v.z*f2 + b1v.w*f3;
            float s2 = a2.x*e0 + a2.y*e1 + a2.z*e2 + a2.w*e3 + b2v.x*f0 + b2v.y*f1 + b2v.z*f2 + b2v.w*f3;
            float s3 = a3.x*e0 + a3.y*e1 + a3.z*e2 + a3.w*e3 + b3v.x*f0 + b3v.y*f1 + b3v.z*f2 + b3v.w*f3;
            s0 = warp_sum(s0); s1 = warp_sum(s1); s2 = warp_sum(s2); s3 = warp_sum(s3);
            if (lane == 0) {
                sfc[j0 + 0] = bd3[j0 + 0] + s0;
                sfc[j0 + 1] = bd3[j0 + 1] + s1;
                sfc[j0 + 2] = bd3[j0 + 2] + s2;
                sfc[j0 + 3] = bd3[j0 + 3] + s3;
            }
        }
        __syncthreads();
    }

    // bias for this block's 8 channels: warp w -> channel cbase+w.
    {
        const int c = cbase + warp;
        const float* p = Ws + c * 134 + 6;
        float w0 = p[lane], w1 = p[lane + 32], w2 = p[lane + 64], w3 = p[lane + 96];
        float v0 = sfc[lane], v1 = sfc[lane + 32],
              v2 = sfc[lane + 64], v3 = sfc[lane + 96];
        float s = warp_sum(w0*v0 + w1*v1 + w2*v2 + w3*v3);
        if (lane == 0) sbias[warp] = bs[c] + s;
    }
    __syncthreads();

    // coefficient blob for the 8 channels (threads 0..7)
    if (t < 8) {
        const int c = cbase + t;
        float w0 = Ws[c * 134 + 0], w1 = Ws[c * 134 + 1], w2 = Ws[c * 134 + 2];
        float w3 = Ws[c * 134 + 3], w4 = Ws[c * 134 + 4], w5 = Ws[c * 134 + 5];
        float A = w0 * sK[0] + w1 * sK[3] + w2 * sK[6];
        float B = w0 * sK[1] + w1 * sK[4] + w2 * sK[7];
        float C = w0 * sK[2] + w1 * sK[5] + w2 * sK[8]
                + A * soff[0] + B * soff[1];
        float bi = sbias[t];
        float* dst = sP + t * 16;
        dst[0]  = A;  dst[1]  = A;
        dst[2]  = B;  dst[3]  = B;
        dst[4]  = C;  dst[5]  = C;
        dst[6]  = w3; dst[7]  = w3;
        dst[8]  = w4; dst[9]  = w4;
        dst[10] = w5; dst[11] = w5;
        dst[12] = bi; dst[13] = bi;
        dst[14] = 0.0f; dst[15] = 0.0f;
    }
    __syncthreads();

    // ---- pixel phase: 2 sequential quads per thread ----
    const int x1 = sbox[0], y1 = sbox[1], x2 = sbox[2], y2 = sbox[3];
    const int qbase = (blk & 31) * 512;    // 512 quads per block

    #pragma unroll 1
    for (int qi = 0; qi < 2; qi++) {
        const int q   = qbase + qi * 256 + t;
        const int p0  = q * 4;
        const int r   = p0 >> 8;
        const int cc0 = p0 & 255;

        float4 dz = *reinterpret_cast<const float4*>(depth + p0);
        const float4* rp = reinterpret_cast<const float4*>(rgb + (size_t)p0 * 3);
        float4 q0 = rp[0], q1 = rp[1], q2 = rp[2];

        u64 u01 = pair2((float)cc0,       (float)(cc0 + 1));
        u64 u23 = pair2((float)(cc0 + 2), (float)(cc0 + 3));
        u64 v2  = pk2((float)r);
        u64 z01 = pair2(dz.x, dz.y), z23 = pair2(dz.z, dz.w);
        u64 r01 = pair2(q0.x, q0.w), r23 = pair2(q1.z, q2.y);
        u64 g01 = pair2(q0.y, q1.x), g23 = pair2(q1.w, q2.z);
        u64 b01 = pair2(q0.z, q1.y), b23 = pair2(q2.x, q2.w);

        const bool rowin = (r >= x1) && (r < x2);
        bool in0 = rowin && (cc0     >= y1) && (cc0     < y2);
        bool in1 = rowin && (cc0 + 1 >= y1) && (cc0 + 1 < y2);
        bool in2 = rowin && (cc0 + 2 >= y1) && (cc0 + 2 < y2);
        bool in3 = rowin && (cc0 + 3 >= y1) && (cc0 + 3 < y2);
        const bool allin = in0 & in1 & in2 & in3;
        u64 m01 = 0, m23 = 0;
        if (!allin) {
            m01 = (in0 ? 0xFFFFFFFFull : 0ull) | (in1 ? 0xFFFFFFFF00000000ull : 0ull);
            m23 = (in2 ? 0xFFFFFFFFull : 0ull) | (in3 ? 0xFFFFFFFF00000000ull : 0ull);
        }

        float* outbase = out + (size_t)cbase * HWPIX + p0;

        #pragma unroll
        for (int cn = 0; cn < 8; cn++) {
            const ulonglong2* cf = reinterpret_cast<const ulonglong2*>(sP + cn * 16);
            ulonglong2 c0 = cf[0];   // A, B
            ulonglong2 c1 = cf[1];   // C, w3
            ulonglong2 c2 = cf[2];   // w4, w5
            ulonglong2 c3 = cf[3];   // bias, 0

            u64 base = fma2(c0.y, v2, c1.x);          // B*v + C''
            u64 t01  = fma2(c0.x, u01, base);
            u64 t23  = fma2(c0.x, u23, base);

            u64 d01 = fma2(c1.y, r01, fma2(c2.x, g01, fma2(c2.y, b01, c3.x)));
            u64 d23 = fma2(c1.y, r23, fma2(c2.x, g23, fma2(c2.y, b23, c3.x)));

            u64 s01 = fma2(z01, t01, d01);
            u64 s23 = fma2(z23, t23, d23);
            if (!allin) { s01 &= m01; s23 &= m23; }

            ulonglong2 o; o.x = s01; o.y = s23;
            *reinterpret_cast<ulonglong2*>(outbase + (size_t)cn * HWPIX) = o;
        }
    }
}

extern "C" void kernel_launch(void* const* d_in, const int* in_sizes, int n_in,
                              void* d_out, int out_size)
{
    const float* rgb   = (const float*)d_in[0];
    const float* depth = (const float*)d_in[1];
    const float* intr  = (const float*)d_in[2];
    const int*   box   = (const int*)  d_in[3];
    const float* be5   = (const float*)d_in[23];
    const float* Wd3   = (const float*)d_in[24];
    const float* bd3   = (const float*)d_in[25];
    const float* Ws    = (const float*)d_in[26];
    const float* bs    = (const float*)d_in[27];
    float* out = (float*)d_out;

    frustum_all_kernel<<<320, 256>>>(rgb, depth, intr, box,
                                     be5, Wd3, bd3, Ws, bs, out);
}

// round 14
// speedup vs baseline: 1.9940x; 1.9940x over previous
#include <cuda_runtime.h>
#include <cuda_bf16.h>

// -----------------------------------------------------------------------------
// FrustumSegmentationNet — collapsed exact-math, ONE kernel, fully parallel
// per-block prep (R11 structure, verbatim).
//
// R0 proof: FPS argmin always selects index 0 -> all groups identical ->
// axis-0 batchnorms collapse feats to the constant fc = bd3 + relu(be5)@Wd3^T.
// Output = per-pixel 6->80 linear with Kinv folded into per-channel (A,B,C)
// + folded bias; zero outside the box.
//
// R14 = R11 + __launch_bounds__(256, 5): cap regs at 51 so 5 blocks/SM are
// resident -> all 640 blocks fit in ONE wave (148*5=740 slots): no ragged
// second-wave tail, prep paid once fully in parallel, occupancy 32->40
// warps/SM. (R13's 2-seq-quad regression was a grid-too-small artifact:
// 320 blocks gave only 2.2 resident blocks/SM.)
// -----------------------------------------------------------------------------

#define HWPIX  65536
#define NCH    80

typedef unsigned long long u64;

__device__ __forceinline__ u64 pk2(float x) {
    u64 r; asm("mov.b64 %0, {%1, %1};" : "=l"(r) : "f"(x)); return r;
}
__device__ __forceinline__ u64 pair2(float lo, float hi) {
    u64 r; asm("mov.b64 %0, {%1, %2};" : "=l"(r) : "f"(lo), "f"(hi)); return r;
}
__device__ __forceinline__ u64 fma2(u64 a, u64 b, u64 c) {
    u64 d; asm("fma.rn.f32x2 %0, %1, %2, %3;" : "=l"(d) : "l"(a), "l"(b), "l"(c));
    return d;
}
__device__ __forceinline__ float warp_sum(float s) {
    #pragma unroll
    for (int off = 16; off > 0; off >>= 1)
        s += __shfl_down_sync(0xFFFFFFFFu, s, off);
    return s;
}

__global__ __launch_bounds__(256, 5)
void frustum_all_kernel(const float* __restrict__ rgb,    // (H,W,3)
                        const float* __restrict__ depth,  // (H,W)
                        const float* __restrict__ intr,   // (3,3)
                        const int*   __restrict__ box,    // (5)
                        const float* __restrict__ be5,    // (256)
                        const float* __restrict__ Wd3,    // (128,256)
                        const float* __restrict__ bd3,    // (128)
                        const float* __restrict__ Ws,     // (80,134)
                        const float* __restrict__ bs,     // (80)
                        float* __restrict__ out)          // (80,H,W)
{
    // blob first (LDS.128-accessed -> 16B aligned):
    // per channel: [A,A, B,B, C,C, w3,w3, w4,w4, w5,w5, bias,bias, 0,0]
    __shared__ __align__(16) float sP[8 * 16];
    __shared__ __align__(16) float sfc[128];
    __shared__ __align__(16) float sbe[256];
    __shared__ __align__(16) float sbias[8];
    __shared__ __align__(16) float sK[12];
    __shared__ __align__(16) float soff[4];
    __shared__ __align__(16) int   sbox[4];

    const int t     = threadIdx.x;
    const int warp  = t >> 5;
    const int lane  = t & 31;
    const int blk   = blockIdx.x;
    const int cbase = (blk >> 6) * 8;      // 64 blocks per channel group

    // ---- per-block prep ----
    float bev = fmaxf(be5[t], 0.0f);
    sbe[t] = bev;
    if (t == 0) {
        float a = intr[0], b = intr[1], c = intr[2];
        float d = intr[3], e = intr[4], f = intr[5];
        float gg = intr[6], h = intr[7], i9 = intr[8];
        float det = a * (e * i9 - f * h) - b * (d * i9 - f * gg) + c * (d * h - e * gg);
        float inv = 1.0f / det;
        sK[0] = (e * i9 - f * h) * inv;  sK[1] = (c * h - b * i9) * inv;  sK[2] = (b * f - c * e) * inv;
        sK[3] = (f * gg - d * i9) * inv; sK[4] = (a * i9 - c * gg) * inv; sK[5] = (c * d - a * f) * inv;
        sK[6] = (d * h - e * gg) * inv;  sK[7] = (b * gg - a * h) * inv;  sK[8] = (a * e - b * d) * inv;
        int b0 = box[0], b1 = box[1], b2 = box[2], b3 = box[3];
        sbox[0] = b0; sbox[1] = b1; sbox[2] = b2; sbox[3] = b3;
        soff[0] = 0.5f - (float)b1;    // u offset (col)
        soff[1] = 0.5f - (float)b0;    // v offset (row)
    }
    const int any_pos = __syncthreads_or(bev > 0.0f);

    if (!any_pos) {
        // fast path (bit-exact): relu(be5) == 0 -> fc = bd3
        if (t < 128) sfc[t] = bd3[t];
        __syncthreads();
    } else {
        // general fallback: fc[j] = bd3[j] + relu(be5) . Wd3[j,:]
        #pragma unroll
        for (int bb = 0; bb < 4; bb++) {
            int j0 = warp * 16 + bb * 4;
            const float4* r0 = reinterpret_cast<const float4*>(Wd3 + (j0 + 0) * 256);
            const float4* r1 = reinterpret_cast<const float4*>(Wd3 + (j0 + 1) * 256);
            const float4* r2 = reinterpret_cast<const float4*>(Wd3 + (j0 + 2) * 256);
            const float4* r3 = reinterpret_cast<const float4*>(Wd3 + (j0 + 3) * 256);
            float4 a0 = r0[lane], b0v = r0[lane + 32];
            float4 a1 = r1[lane], b1v = r1[lane + 32];
            float4 a2 = r2[lane], b2v = r2[lane + 32];
            float4 a3 = r3[lane], b3v = r3[lane + 32];
            int k0 = 4 * lane, k1 = 128 + 4 * lane;
            float e0 = sbe[k0], e1 = sbe[k0+1], e2 = sbe[k0+2], e3 = sbe[k0+3];
            float f0 = sbe[k1], f1 = sbe[k1+1], f2 = sbe[k1+2], f3 = sbe[k1+3];
            float s0 = a0.x*e0 + a0.y*e1 + a0.z*e2 + a0.w*e3 + b0v.x*f0 + b0v.y*f1 + b0v.z*f2 + b0v.w*f3;
            float s1 = a1.x*e0 + a1.y*e1 + a1.z*e2 + a1.w*e3 + b1v.x*f0 + b1v.y*f1 + b1v.z*f2 + b1v.w*f3;
            float s2 = a2.x*e0 + a2.y*e1 + a2.z*e2 + a2.w*e3 + b2v.x*f0 + b2v.y*f1 + b2v.z*f2 + b2v.w*f3;
            float s3 = a3.x*e0 + a3.y*e1 + a3.z*e2 + a3.w*e3 + b3v.x*f0 + b3v.y*f1 + b3v.z*f2 + b3v.w*f3;
            s0 = warp_sum(s0); s1 = warp_sum(s1); s2 = warp_sum(s2); s3 = warp_sum(s3);
            if (lane == 0) {
                sfc[j0 + 0] = bd3[j0 + 0] + s0;
                sfc[j0 + 1] = bd3[j0 + 1] + s1;
                sfc[j0 + 2] = bd3[j0 + 2] + s2;
                sfc[j0 + 3] = bd3[j0 + 3] + s3;
            }
        }
        __syncthreads();
    }

    // bias for this block's 8 channels: warp w -> channel cbase+w.
    {
        const int c = cbase + warp;
        const float* p = Ws + c * 134 + 6;
        float w0 = p[lane], w1 = p[lane + 32], w2 = p[lane + 64], w3 = p[lane + 96];
        float v0 = sfc[lane], v1 = sfc[lane + 32],
              v2 = sfc[lane + 64], v3 = sfc[lane + 96];
        float s = warp_sum(w0*v0 + w1*v1 + w2*v2 + w3*v3);
        if (lane == 0) sbias[warp] = bs[c] + s;
    }
    __syncthreads();

    // coefficient blob for the 8 channels (threads 0..7)
    if (t < 8) {
        const int c = cbase + t;
        float w0 = Ws[c * 134 + 0], w1 = Ws[c * 134 + 1], w2 = Ws[c * 134 + 2];
        float w3 = Ws[c * 134 + 3], w4 = Ws[c * 134 + 4], w5 = Ws[c * 134 + 5];
        float A = w0 * sK[0] + w1 * sK[3] + w2 * sK[6];
        float B = w0 * sK[1] + w1 * sK[4] + w2 * sK[7];
        float C = w0 * sK[2] + w1 * sK[5] + w2 * sK[8]
                + A * soff[0] + B * soff[1];
        float bi = sbias[t];
        float* dst = sP + t * 16;
        dst[0]  = A;  dst[1]  = A;
        dst[2]  = B;  dst[3]  = B;
        dst[4]  = C;  dst[5]  = C;
        dst[6]  = w3; dst[7]  = w3;
        dst[8]  = w4; dst[9]  = w4;
        dst[10] = w5; dst[11] = w5;
        dst[12] = bi; dst[13] = bi;
        dst[14] = 0.0f; dst[15] = 0.0f;
    }
    __syncthreads();

    // ---- pixel phase (R4/R11-proven body, 1 quad/thread) ----
    const int q   = (blk * 256 + t) & 16383;
    const int p0  = q * 4;
    const int r   = p0 >> 8;
    const int cc0 = p0 & 255;

    const int x1 = sbox[0], y1 = sbox[1], x2 = sbox[2], y2 = sbox[3];

    float4 dz = *reinterpret_cast<const float4*>(depth + p0);
    const float4* rp = reinterpret_cast<const float4*>(rgb + (size_t)p0 * 3);
    float4 q0 = rp[0], q1 = rp[1], q2 = rp[2];

    u64 u01 = pair2((float)cc0,       (float)(cc0 + 1));
    u64 u23 = pair2((float)(cc0 + 2), (float)(cc0 + 3));
    u64 v2  = pk2((float)r);
    u64 z01 = pair2(dz.x, dz.y), z23 = pair2(dz.z, dz.w);
    u64 r01 = pair2(q0.x, q0.w), r23 = pair2(q1.z, q2.y);
    u64 g01 = pair2(q0.y, q1.x), g23 = pair2(q1.w, q2.z);
    u64 b01 = pair2(q0.z, q1.y), b23 = pair2(q2.x, q2.w);

    const bool rowin = (r >= x1) && (r < x2);
    bool in0 = rowin && (cc0     >= y1) && (cc0     < y2);
    bool in1 = rowin && (cc0 + 1 >= y1) && (cc0 + 1 < y2);
    bool in2 = rowin && (cc0 + 2 >= y1) && (cc0 + 2 < y2);
    bool in3 = rowin && (cc0 + 3 >= y1) && (cc0 + 3 < y2);
    const bool allin = in0 & in1 & in2 & in3;
    u64 m01 = 0, m23 = 0;
    if (!allin) {
        m01 = (in0 ? 0xFFFFFFFFull : 0ull) | (in1 ? 0xFFFFFFFF00000000ull : 0ull);
        m23 = (in2 ? 0xFFFFFFFFull : 0ull) | (in3 ? 0xFFFFFFFF00000000ull : 0ull);
    }

    float* outbase = out + (size_t)cbase * HWPIX + p0;

    #pragma unroll
    for (int cn = 0; cn < 8; cn++) {
        const ulonglong2* cf = reinterpret_cast<const ulonglong2*>(sP + cn * 16);
        ulonglong2 c0 = cf[0];   // A, B
        ulonglong2 c1 = cf[1];   // C, w3
        ulonglong2 c2 = cf[2];   // w4, w5
        ulonglong2 c3 = cf[3];   // bias, 0

        u64 base = fma2(c0.y, v2, c1.x);          // B*v + C''
        u64 t01  = fma2(c0.x, u01, base);
        u64 t23  = fma2(c0.x, u23, base);

        u64 d01 = fma2(c1.y, r01, fma2(c2.x, g01, fma2(c2.y, b01, c3.x)));
        u64 d23 = fma2(c1.y, r23, fma2(c2.x, g23, fma2(c2.y, b23, c3.x)));

        u64 s01 = fma2(z01, t01, d01);
        u64 s23 = fma2(z23, t23, d23);
        if (!allin) { s01 &= m01; s23 &= m23; }

        ulonglong2 o; o.x = s01; o.y = s23;
        *reinterpret_cast<ulonglong2*>(outbase + (size_t)cn * HWPIX) = o;
    }
}

extern "C" void kernel_launch(void* const* d_in, const int* in_sizes, int n_in,
                              void* d_out, int out_size)
{
    const float* rgb   = (const float*)d_in[0];
    const float* depth = (const float*)d_in[1];
    const float* intr  = (const float*)d_in[2];
    const int*   box   = (const int*)  d_in[3];
    const float* be5   = (const float*)d_in[23];
    const float* Wd3   = (const float*)d_in[24];
    const float* bd3   = (const float*)d_in[25];
    const float* Ws    = (const float*)d_in[26];
    const float* bs    = (const float*)d_in[27];
    float* out = (float*)d_out;

    frustum_all_kernel<<<640, 256>>>(rgb, depth, intr, box,
                                     be5, Wd3, bd3, Ws, bs, out);
}